// round 13
// baseline (speedup 1.0000x reference)
#include <cuda_runtime.h>
#include <cuda_fp16.h>
#include <cstdint>
#include <math.h>

#define NTOK 8192
#define CDIM 768
#define HDIM 3072
#define H2   (2*HDIM)
#define NEXP 16
#define TOPK 4
#define TILE_M 128
#define MAX_TILES 336
#define MAX_ROWS (MAX_TILES*TILE_M)

#define KC 16
#define STAGES 6
#define BLK_N 256
#define FC1_NOUT 128
#define FC1_COLS (HDIM/FC1_NOUT)   // 24
#define FC2_COLS (CDIM/BLK_N)      // 3
#define A_BYTES (128*16*2)         // 4096 per stage
#define B_BYTES (16*256*2)         // 8192 per stage
#define STG_BYTES (A_BYTES + B_BYTES)   // 12288
#define FC_SMEM (STAGES*STG_BYTES)      // 72KB

// ------------------- device scratch -------------------
__device__ __align__(16) __half g_xh[(size_t)NTOK*CDIM];
__device__ __align__(16) __half g_wfc_h[(size_t)(NEXP+1)*CDIM*H2];
__device__ __align__(16) __half g_wpj_h[(size_t)(NEXP+1)*HDIM*CDIM];
__device__ __align__(16) __half g_act[(size_t)MAX_ROWS*HDIM];
__device__ float g_part[(size_t)MAX_ROWS*CDIM];
__device__ int   g_row_token[MAX_ROWS];
__device__ float g_row_weight[MAX_ROWS];
__device__ int   g_tok_rows[NTOK*(TOPK+1)];
__device__ int   g_counts[NEXP];
__device__ int   g_cursor[NEXP];
__device__ int   g_offset[NEXP+1];
__device__ int   g_tile_expert[MAX_TILES];
__device__ int   g_tile_row0[MAX_TILES];
__device__ int   g_num_tiles;
__device__ int   g_topi[NTOK*TOPK];
__device__ float g_topw[NTOK*TOPK];

// ------------------- helpers -------------------
__device__ __forceinline__ float silu_f(float x){ return x / (1.0f + expf(-x)); }

__device__ __forceinline__ uint32_t smem_u32(const void* p){
    uint32_t a;
    asm("{ .reg .u64 t; cvta.to.shared.u64 t, %1; cvt.u32.u64 %0, t; }" : "=r"(a) : "l"(p));
    return a;
}

#define CP16(dst, src) \
    asm volatile("cp.async.cg.shared.global [%0], [%1], 16;" :: "r"(dst), "l"(src))
#define CP_COMMIT() asm volatile("cp.async.commit_group;")

#define LDSM4(r0,r1,r2,r3, addr) \
    asm volatile("ldmatrix.sync.aligned.m8n8.x4.shared.b16 {%0,%1,%2,%3}, [%4];" \
        : "=r"(r0),"=r"(r1),"=r"(r2),"=r"(r3) : "r"(addr))
#define LDSM2T(r0,r1, addr) \
    asm volatile("ldmatrix.sync.aligned.m8n8.x2.trans.shared.b16 {%0,%1}, [%2];" \
        : "=r"(r0),"=r"(r1) : "r"(addr))

__device__ __forceinline__ void mma_f16(float* d, const uint32_t* a, const uint32_t* b){
    asm volatile(
        "mma.sync.aligned.m16n8k16.row.col.f32.f16.f16.f32 "
        "{%0,%1,%2,%3}, {%4,%5,%6,%7}, {%8,%9}, {%0,%1,%2,%3};"
        : "+f"(d[0]), "+f"(d[1]), "+f"(d[2]), "+f"(d[3])
        : "r"(a[0]), "r"(a[1]), "r"(a[2]), "r"(a[3]), "r"(b[0]), "r"(b[1]));
}

// ------------------- prep: convert x + weights to fp16, init state -------------
__global__ void k_prep(const float* __restrict__ x,
                       const float* __restrict__ wfc_sh,
                       const float* __restrict__ wfc_ex,
                       const float* __restrict__ wpj_sh,
                       const float* __restrict__ wpj_ex){
    int i0 = blockIdx.x*blockDim.x + threadIdx.x;
    int stride = gridDim.x*blockDim.x;
    const size_t NFC = (size_t)CDIM*H2;
    const size_t NPJ = (size_t)HDIM*CDIM;

    for (size_t i = i0; i < (size_t)NTOK*CDIM; i += stride) g_xh[i] = __float2half_rn(x[i]);
    for (size_t i = i0; i < (size_t)NEXP*NFC;  i += stride) g_wfc_h[i] = __float2half_rn(wfc_ex[i]);
    for (size_t i = i0; i < NFC;               i += stride) g_wfc_h[(size_t)NEXP*NFC + i] = __float2half_rn(wfc_sh[i]);
    for (size_t i = i0; i < (size_t)NEXP*NPJ;  i += stride) g_wpj_h[i] = __float2half_rn(wpj_ex[i]);
    for (size_t i = i0; i < NPJ;               i += stride) g_wpj_h[(size_t)NEXP*NPJ + i] = __float2half_rn(wpj_sh[i]);

    for (int i = i0; i < MAX_ROWS; i += stride) g_row_token[i] = 0;
    if (i0 < NEXP) g_counts[i0] = 0;
}

// ------------------- gate -------------------
__global__ void k_gate(const float* __restrict__ x,
                       const float* __restrict__ wg,
                       const float* __restrict__ bias){
    int warp = (blockIdx.x*blockDim.x + threadIdx.x) >> 5;
    int lane = threadIdx.x & 31;
    if (warp >= NTOK) return;
    const float* xr = x + (size_t)warp*CDIM;

    int e = lane & 15, half = lane >> 4;
    float acc = 0.0f;
    int c0 = half*(CDIM/2);
    for (int c = c0; c < c0 + CDIM/2; ++c) acc += xr[c]*wg[c*NEXP + e];
    acc += __shfl_down_sync(0xFFFFFFFFu, acc, 16);

    float gate = -1.0f;
    if (lane < 16) gate = 1.0f/(1.0f + expf(-(acc + bias[e])));

    int rank = 0;
    #pragma unroll
    for (int j = 0; j < 16; ++j){
        float gj = __shfl_sync(0xFFFFFFFFu, gate, j);
        if (lane < 16) rank += (gj > gate) || (gj == gate && j < e);
    }
    bool sel = (lane < 16) && (rank < TOPK);
    float sv = sel ? gate : 0.0f;
    #pragma unroll
    for (int o = 8; o >= 1; o >>= 1) sv += __shfl_xor_sync(0xFFFFFFFFu, sv, o);
    unsigned ballot = __ballot_sync(0xFFFFFFFFu, sel);
    if (sel){
        int kidx = __popc(ballot & ((1u << lane) - 1u));
        g_topi[warp*TOPK + kidx] = e;
        g_topw[warp*TOPK + kidx] = gate/sv;
        atomicAdd(&g_counts[e], 1);
    }
}

// ------------------- scan + fill fused ----------------
__global__ void __launch_bounds__(1024, 1) k_scanfill(){
    if (threadIdx.x == 0){
        int off = 0, nt = 0;
        for (int e = 0; e <= NEXP; ++e){
            int cnt = (e < NEXP) ? g_counts[e] : NTOK;
            g_offset[e] = off;
            if (e < NEXP) g_cursor[e] = off;
            int tiles = (cnt + TILE_M - 1)/TILE_M;
            for (int i = 0; i < tiles; ++i){
                g_tile_expert[nt] = e;
                g_tile_row0[nt] = off + i*TILE_M;
                nt++;
            }
            off += tiles*TILE_M;
        }
        g_num_tiles = nt;
    }
    __syncthreads();
    for (int idx = threadIdx.x; idx < NTOK*(TOPK+1); idx += 1024){
        int t = idx/(TOPK+1), j = idx%(TOPK+1);
        if (j < TOPK){
            int e = g_topi[t*TOPK + j];
            float w = g_topw[t*TOPK + j];
            int r = atomicAdd(&g_cursor[e], 1);
            g_row_token[r] = t;
            g_row_weight[r] = w;
            g_tok_rows[t*(TOPK+1) + j] = r;
        } else {
            int r = g_offset[NEXP] + t;
            g_row_token[r] = t;
            g_row_weight[r] = 1.0f;
            g_tok_rows[t*(TOPK+1) + j] = r;
        }
    }
}

// ------------------- FC1: swiglu(Xg @ Wfc), fp16 m16n8k16, CTA 128x256 ----------
// 8 warps (2M x 4N), warp tile 64x64; B fragments double-buffered (software
// pipelined one ks ahead), A fragments loaded per-iter.
__global__ void __launch_bounds__(256, 1) k_fc1(){
    int bx = blockIdx.x;
    int tile = bx / FC1_COLS, jb = (bx % FC1_COLS)*FC1_NOUT;
    if (tile >= g_num_tiles) return;
    int e = g_tile_expert[tile], row0 = g_tile_row0[tile];
    const __half* wbase = g_wfc_h + (size_t)e*CDIM*H2;

    extern __shared__ char smc[];
    uint32_t sb = smem_u32(smc);

    int tid = threadIdx.x, lane = tid & 31, w = tid >> 5;
    int wm = w & 1, wn = w >> 1;
    int m0 = wm*64, n0w = wn*8;
    int r = lane >> 2;

    // cp.async A: thread -> (row am, half-segment ah)
    int am = tid >> 1, ah = tid & 1;
    int tokA = g_row_token[row0 + am];
    const __half* asrc = g_xh + (size_t)tokA*CDIM + ah*8;
    uint32_t adst = (uint32_t)(am*32 + ((ah ^ ((am >> 2) & 1)) << 4));

    // cp.async B: 2 chunks/thread
    const __half* bsrc[2]; uint32_t bdst[2];
    #pragma unroll
    for (int i = 0; i < 2; i++){
        int idx = tid + i*256;
        int bk = idx >> 5, nb = idx & 31;
        int col0 = (nb & 1) ? (HDIM + jb + (nb >> 1)*8) : (jb + (nb >> 1)*8);
        bsrc[i] = wbase + (size_t)bk*H2 + col0;
        bdst[i] = (uint32_t)(A_BYTES + bk*512 + ((nb ^ (bk & 7)) << 4));
    }

    #pragma unroll
    for (int s = 0; s < STAGES-1; s++){
        uint32_t so = sb + s*STG_BYTES;
        CP16(so + adst, asrc + s*KC);
        #pragma unroll
        for (int i = 0; i < 2; i++)
            CP16(so + bdst[i], bsrc[i] + (size_t)s*KC*H2);
        CP_COMMIT();
    }

    float acc[4][8][4];
    #pragma unroll
    for (int i = 0; i < 4; i++)
        #pragma unroll
        for (int j = 0; j < 8; j++)
            #pragma unroll
            for (int q = 0; q < 4; q++) acc[i][j][q] = 0.0f;

    // ldmatrix per-lane offsets
    uint32_t aoff[4];
    {
        int li = lane & 7, msel = (lane >> 3) & 1, h = (lane >> 4) & 1;
        #pragma unroll
        for (int mi = 0; mi < 4; mi++){
            int m = m0 + mi*16 + msel*8 + li;
            aoff[mi] = (uint32_t)(m*32 + ((h ^ ((m >> 2) & 1)) << 4));
        }
    }
    uint32_t boff[8];
    {
        int kk = lane & 15;
        #pragma unroll
        for (int ni = 0; ni < 8; ni++){
            int nb = n0w + ni;
            boff[ni] = (uint32_t)(A_BYTES + kk*512 + ((nb ^ (kk & 7)) << 4));
        }
    }

    // pre-loop: stage 0 ready -> load B frags for ks=0
    asm volatile("cp.async.wait_group %0;" :: "n"(STAGES-2) : "memory");
    __syncthreads();
    uint32_t bfr[2][8][2];
    #pragma unroll
    for (int ni = 0; ni < 8; ni++)
        LDSM2T(bfr[0][ni][0], bfr[0][ni][1], sb + boff[ni]);

    const int nK = CDIM/KC;   // 48
    for (int ks = 0; ks < nK; ks++){
        int cur = ks & 1, nxt = cur ^ 1;
        int t = ks + STAGES - 1;
        if (t < nK){
            uint32_t so = sb + (t % STAGES)*STG_BYTES;
            CP16(so + adst, asrc + t*KC);
            #pragma unroll
            for (int i = 0; i < 2; i++)
                CP16(so + bdst[i], bsrc[i] + (size_t)t*KC*H2);
        }
        CP_COMMIT();
        asm volatile("cp.async.wait_group %0;" :: "n"(STAGES-2) : "memory");
        __syncthreads();

        // A frags for current ks
        uint32_t st_cur = sb + (ks % STAGES)*STG_BYTES;
        uint32_t a[4][4];
        #pragma unroll
        for (int mi = 0; mi < 4; mi++)
            LDSM4(a[mi][0], a[mi][1], a[mi][2], a[mi][3], st_cur + aoff[mi]);
        // B frags for next ks (hidden under MMAs below)
        if (ks + 1 < nK){
            uint32_t st_nxt = sb + ((ks + 1) % STAGES)*STG_BYTES;
            #pragma unroll
            for (int ni = 0; ni < 8; ni++)
                LDSM2T(bfr[nxt][ni][0], bfr[nxt][ni][1], st_nxt + boff[ni]);
        }
        #pragma unroll
        for (int mi = 0; mi < 4; mi++)
            #pragma unroll
            for (int ni = 0; ni < 8; ni++)
                mma_f16(acc[mi][ni], a[mi], bfr[cur][ni]);
    }

    // epilogue: swiglu pairs (ni even = gate, ni+1 = val), write fp16
    int c2 = (lane & 3)*2;
    #pragma unroll
    for (int mi = 0; mi < 4; mi++){
        int ra = row0 + m0 + mi*16 + r;
        #pragma unroll
        for (int fe = 0; fe < 8; fe += 2){
            float* ag = acc[mi][fe];
            float* av = acc[mi][fe + 1];
            int ocol = jb + (4*wn + (fe >> 1))*8 + c2;
            __half2 h0 = __floats2half2_rn(silu_f(ag[0])*av[0], silu_f(ag[1])*av[1]);
            __half2 h1 = __floats2half2_rn(silu_f(ag[2])*av[2], silu_f(ag[3])*av[3]);
            *(__half2*)(g_act + (size_t)ra*HDIM + ocol) = h0;
            *(__half2*)(g_act + (size_t)(ra + 8)*HDIM + ocol) = h1;
        }
    }
}

// ------------------- FC2: act @ Wproj -> g_part, fp16 m16n8k16 -------------------
__global__ void __launch_bounds__(256, 1) k_fc2(){
    int bx = blockIdx.x;
    int tile = bx / FC2_COLS, jb = (bx % FC2_COLS)*BLK_N;
    if (tile >= g_num_tiles) return;
    int e = g_tile_expert[tile], row0 = g_tile_row0[tile];
    const __half* wbase = g_wpj_h + (size_t)e*HDIM*CDIM;

    extern __shared__ char smc[];
    uint32_t sb = smem_u32(smc);

    int tid = threadIdx.x, lane = tid & 31, w = tid >> 5;
    int wm = w & 1, wn = w >> 1;
    int m0 = wm*64, n0w = wn*8;
    int r = lane >> 2;

    int am = tid >> 1, ah = tid & 1;
    const __half* asrc = g_act + (size_t)(row0 + am)*HDIM + ah*8;
    uint32_t adst = (uint32_t)(am*32 + ((ah ^ ((am >> 2) & 1)) << 4));

    const __half* bsrc[2]; uint32_t bdst[2];
    #pragma unroll
    for (int i = 0; i < 2; i++){
        int idx = tid + i*256;
        int bk = idx >> 5, nb = idx & 31;
        bsrc[i] = wbase + (size_t)bk*CDIM + jb + nb*8;
        bdst[i] = (uint32_t)(A_BYTES + bk*512 + ((nb ^ (bk & 7)) << 4));
    }

    #pragma unroll
    for (int s = 0; s < STAGES-1; s++){
        uint32_t so = sb + s*STG_BYTES;
        CP16(so + adst, asrc + s*KC);
        #pragma unroll
        for (int i = 0; i < 2; i++)
            CP16(so + bdst[i], bsrc[i] + (size_t)s*KC*CDIM);
        CP_COMMIT();
    }

    float acc[4][8][4];
    #pragma unroll
    for (int i = 0; i < 4; i++)
        #pragma unroll
        for (int j = 0; j < 8; j++)
            #pragma unroll
            for (int q = 0; q < 4; q++) acc[i][j][q] = 0.0f;

    uint32_t aoff[4];
    {
        int li = lane & 7, msel = (lane >> 3) & 1, h = (lane >> 4) & 1;
        #pragma unroll
        for (int mi = 0; mi < 4; mi++){
            int m = m0 + mi*16 + msel*8 + li;
            aoff[mi] = (uint32_t)(m*32 + ((h ^ ((m >> 2) & 1)) << 4));
        }
    }
    uint32_t boff[8];
    {
        int kk = lane & 15;
        #pragma unroll
        for (int ni = 0; ni < 8; ni++){
            int nb = n0w + ni;
            boff[ni] = (uint32_t)(A_BYTES + kk*512 + ((nb ^ (kk & 7)) << 4));
        }
    }

    asm volatile("cp.async.wait_group %0;" :: "n"(STAGES-2) : "memory");
    __syncthreads();
    uint32_t bfr[2][8][2];
    #pragma unroll
    for (int ni = 0; ni < 8; ni++)
        LDSM2T(bfr[0][ni][0], bfr[0][ni][1], sb + boff[ni]);

    const int nK = HDIM/KC;   // 192
    for (int ks = 0; ks < nK; ks++){
        int cur = ks & 1, nxt = cur ^ 1;
        int t = ks + STAGES - 1;
        if (t < nK){
            uint32_t so = sb + (t % STAGES)*STG_BYTES;
            CP16(so + adst, asrc + t*KC);
            #pragma unroll
            for (int i = 0; i < 2; i++)
                CP16(so + bdst[i], bsrc[i] + (size_t)t*KC*CDIM);
        }
        CP_COMMIT();
        asm volatile("cp.async.wait_group %0;" :: "n"(STAGES-2) : "memory");
        __syncthreads();

        uint32_t st_cur = sb + (ks % STAGES)*STG_BYTES;
        uint32_t a[4][4];
        #pragma unroll
        for (int mi = 0; mi < 4; mi++)
            LDSM4(a[mi][0], a[mi][1], a[mi][2], a[mi][3], st_cur + aoff[mi]);
        if (ks + 1 < nK){
            uint32_t st_nxt = sb + ((ks + 1) % STAGES)*STG_BYTES;
            #pragma unroll
            for (int ni = 0; ni < 8; ni++)
                LDSM2T(bfr[nxt][ni][0], bfr[nxt][ni][1], st_nxt + boff[ni]);
        }
        #pragma unroll
        for (int mi = 0; mi < 4; mi++)
            #pragma unroll
            for (int ni = 0; ni < 8; ni++)
                mma_f16(acc[mi][ni], a[mi], bfr[cur][ni]);
    }

    int c2 = (lane & 3)*2;
    #pragma unroll
    for (int mi = 0; mi < 4; mi++){
        int ra = row0 + m0 + mi*16 + r;
        #pragma unroll
        for (int ni = 0; ni < 8; ni++){
            int ocol = jb + wn*64 + ni*8 + c2;
            float2 o0, o1;
            o0.x = acc[mi][ni][0]; o0.y = acc[mi][ni][1];
            o1.x = acc[mi][ni][2]; o1.y = acc[mi][ni][3];
            *(float2*)(g_part + (size_t)ra*CDIM + ocol) = o0;
            *(float2*)(g_part + (size_t)(ra + 8)*CDIM + ocol) = o1;
        }
    }
}

// ------------------- gather: out[t] = sum_j w_j * part[r_j] -------------------
__global__ void k_gather(float* __restrict__ out){
    __shared__ int rs[TOPK+1];
    __shared__ float ws[TOPK+1];
    int t = blockIdx.x;
    if (threadIdx.x < TOPK+1){
        int r = g_tok_rows[t*(TOPK+1) + threadIdx.x];
        rs[threadIdx.x] = r;
        ws[threadIdx.x] = g_row_weight[r];
    }
    __syncthreads();
    int c = threadIdx.x*4;
    float4 acc = make_float4(0.f, 0.f, 0.f, 0.f);
    #pragma unroll
    for (int j = 0; j < TOPK+1; j++){
        const float4 p = *(const float4*)(g_part + (size_t)rs[j]*CDIM + c);
        float w = ws[j];
        acc.x += w*p.x; acc.y += w*p.y; acc.z += w*p.z; acc.w += w*p.w;
    }
    *(float4*)(out + (size_t)t*CDIM + c) = acc;
}

// ------------------- launch -------------------
extern "C" void kernel_launch(void* const* d_in, const int* in_sizes, int n_in,
                              void* d_out, int out_size){
    const float* x              = (const float*)d_in[0];
    const float* w_shared_fc    = (const float*)d_in[1];
    const float* w_shared_proj  = (const float*)d_in[2];
    const float* w_experts_fc   = (const float*)d_in[3];
    const float* w_experts_proj = (const float*)d_in[4];
    const float* w_gate         = (const float*)d_in[5];
    const float* expert_bias    = (const float*)d_in[6];
    float* out = (float*)d_out;

    cudaFuncSetAttribute(k_fc1, cudaFuncAttributeMaxDynamicSharedMemorySize, FC_SMEM);
    cudaFuncSetAttribute(k_fc2, cudaFuncAttributeMaxDynamicSharedMemorySize, FC_SMEM);

    // launch #1: conversions + init fused
    k_prep<<<2368, 256>>>(x, w_shared_fc, w_experts_fc, w_shared_proj, w_experts_proj);
    // launch #2
    k_gate<<<NTOK/8, 256>>>(x, w_gate, expert_bias);
    // launch #3
    k_scanfill<<<1, 1024>>>();
    // launch #4  <- ncu captures this one
    k_fc1<<<MAX_TILES*FC1_COLS, 256, FC_SMEM>>>();
    // launch #5
    k_fc2<<<MAX_TILES*FC2_COLS, 256, FC_SMEM>>>();
    // launch #6
    k_gather<<<NTOK, CDIM/4>>>(out);
}

// round 14
// speedup vs baseline: 1.2292x; 1.2292x over previous
#include <cuda_runtime.h>
#include <cuda_fp16.h>
#include <cstdint>
#include <math.h>

#define NTOK 8192
#define CDIM 768
#define HDIM 3072
#define H2   (2*HDIM)
#define NEXP 16
#define TOPK 4
#define TILE_M 128
#define MAX_TILES 336
#define MAX_ROWS (MAX_TILES*TILE_M)

#define KC 16
#define STAGES 4
#define BLK_N 256
#define FC1_NOUT 128
#define FC1_COLS (HDIM/FC1_NOUT)   // 24
#define FC2_COLS (CDIM/BLK_N)      // 3
#define A_BYTES (128*16*2)         // 4096 per stage
#define B_BYTES (16*256*2)         // 8192 per stage
#define STG_BYTES (A_BYTES + B_BYTES)   // 12288
#define FC_SMEM (STAGES*STG_BYTES)      // 48KB

// ------------------- device scratch -------------------
__device__ __align__(16) __half g_xh[(size_t)NTOK*CDIM];
__device__ __align__(16) __half g_wfc_h[(size_t)(NEXP+1)*CDIM*H2];
__device__ __align__(16) __half g_wpj_h[(size_t)(NEXP+1)*HDIM*CDIM];
__device__ __align__(16) __half g_act[(size_t)MAX_ROWS*HDIM];
__device__ float g_part[(size_t)MAX_ROWS*CDIM];
__device__ int   g_row_token[MAX_ROWS];
__device__ float g_row_weight[MAX_ROWS];
__device__ int   g_tok_rows[NTOK*(TOPK+1)];
__device__ int   g_counts[NEXP];
__device__ int   g_cursor[NEXP];
__device__ int   g_offset[NEXP+1];
__device__ int   g_tile_expert[MAX_TILES];
__device__ int   g_tile_row0[MAX_TILES];
__device__ int   g_num_tiles;
__device__ int   g_topi[NTOK*TOPK];
__device__ float g_topw[NTOK*TOPK];

// ------------------- helpers -------------------
__device__ __forceinline__ float silu_f(float x){ return x / (1.0f + expf(-x)); }

__device__ __forceinline__ uint32_t smem_u32(const void* p){
    uint32_t a;
    asm("{ .reg .u64 t; cvta.to.shared.u64 t, %1; cvt.u32.u64 %0, t; }" : "=r"(a) : "l"(p));
    return a;
}

#define CP16(dst, src) \
    asm volatile("cp.async.cg.shared.global [%0], [%1], 16;" :: "r"(dst), "l"(src))
#define CP_COMMIT() asm volatile("cp.async.commit_group;")

#define LDSM4(r0,r1,r2,r3, addr) \
    asm volatile("ldmatrix.sync.aligned.m8n8.x4.shared.b16 {%0,%1,%2,%3}, [%4];" \
        : "=r"(r0),"=r"(r1),"=r"(r2),"=r"(r3) : "r"(addr))
#define LDSM2T(r0,r1, addr) \
    asm volatile("ldmatrix.sync.aligned.m8n8.x2.trans.shared.b16 {%0,%1}, [%2];" \
        : "=r"(r0),"=r"(r1) : "r"(addr))

__device__ __forceinline__ void mma_f16(float* d, const uint32_t* a, const uint32_t* b){
    asm volatile(
        "mma.sync.aligned.m16n8k16.row.col.f32.f16.f16.f32 "
        "{%0,%1,%2,%3}, {%4,%5,%6,%7}, {%8,%9}, {%0,%1,%2,%3};"
        : "+f"(d[0]), "+f"(d[1]), "+f"(d[2]), "+f"(d[3])
        : "r"(a[0]), "r"(a[1]), "r"(a[2]), "r"(a[3]), "r"(b[0]), "r"(b[1]));
}

// ------------------- prep: vectorized fp32->fp16 conversion + init -------------
__device__ __forceinline__ void cvt_stream(const float* __restrict__ src,
                                           __half* __restrict__ dst,
                                           size_t n4, int i0, int stride){
    // n4 = number of float4 groups
    const float4* s4 = (const float4*)src;
    for (size_t i = i0; i < n4; i += stride){
        float4 v = s4[i];
        __half2 h0 = __floats2half2_rn(v.x, v.y);
        __half2 h1 = __floats2half2_rn(v.z, v.w);
        uint32_t u0 = *(uint32_t*)&h0, u1 = *(uint32_t*)&h1;
        uint2 pack = make_uint2(u0, u1);
        *(uint2*)(dst + i*4) = pack;
    }
}

__global__ void k_prep(const float* __restrict__ x,
                       const float* __restrict__ wfc_sh,
                       const float* __restrict__ wfc_ex,
                       const float* __restrict__ wpj_sh,
                       const float* __restrict__ wpj_ex){
    int i0 = blockIdx.x*blockDim.x + threadIdx.x;
    int stride = gridDim.x*blockDim.x;
    const size_t NFC = (size_t)CDIM*H2;
    const size_t NPJ = (size_t)HDIM*CDIM;

    cvt_stream(x,      g_xh,                        ((size_t)NTOK*CDIM) >> 2, i0, stride);
    cvt_stream(wfc_ex, g_wfc_h,                     ((size_t)NEXP*NFC) >> 2,  i0, stride);
    cvt_stream(wfc_sh, g_wfc_h + (size_t)NEXP*NFC,  NFC >> 2,                 i0, stride);
    cvt_stream(wpj_ex, g_wpj_h,                     ((size_t)NEXP*NPJ) >> 2,  i0, stride);
    cvt_stream(wpj_sh, g_wpj_h + (size_t)NEXP*NPJ,  NPJ >> 2,                 i0, stride);

    for (int i = i0; i < MAX_ROWS/4; i += stride)
        *(int4*)(g_row_token + i*4) = make_int4(0, 0, 0, 0);
    if (i0 < NEXP) g_counts[i0] = 0;
}

// ------------------- gate -------------------
__global__ void k_gate(const float* __restrict__ x,
                       const float* __restrict__ wg,
                       const float* __restrict__ bias){
    int warp = (blockIdx.x*blockDim.x + threadIdx.x) >> 5;
    int lane = threadIdx.x & 31;
    if (warp >= NTOK) return;
    const float* xr = x + (size_t)warp*CDIM;

    int e = lane & 15, half = lane >> 4;
    float acc = 0.0f;
    int c0 = half*(CDIM/2);
    for (int c = c0; c < c0 + CDIM/2; ++c) acc += xr[c]*wg[c*NEXP + e];
    acc += __shfl_down_sync(0xFFFFFFFFu, acc, 16);

    float gate = -1.0f;
    if (lane < 16) gate = 1.0f/(1.0f + expf(-(acc + bias[e])));

    int rank = 0;
    #pragma unroll
    for (int j = 0; j < 16; ++j){
        float gj = __shfl_sync(0xFFFFFFFFu, gate, j);
        if (lane < 16) rank += (gj > gate) || (gj == gate && j < e);
    }
    bool sel = (lane < 16) && (rank < TOPK);
    float sv = sel ? gate : 0.0f;
    #pragma unroll
    for (int o = 8; o >= 1; o >>= 1) sv += __shfl_xor_sync(0xFFFFFFFFu, sv, o);
    unsigned ballot = __ballot_sync(0xFFFFFFFFu, sel);
    if (sel){
        int kidx = __popc(ballot & ((1u << lane) - 1u));
        g_topi[warp*TOPK + kidx] = e;
        g_topw[warp*TOPK + kidx] = gate/sv;
        atomicAdd(&g_counts[e], 1);
    }
}

// ------------------- scan + fill fused ----------------
__global__ void __launch_bounds__(1024, 1) k_scanfill(){
    if (threadIdx.x == 0){
        int off = 0, nt = 0;
        for (int e = 0; e <= NEXP; ++e){
            int cnt = (e < NEXP) ? g_counts[e] : NTOK;
            g_offset[e] = off;
            if (e < NEXP) g_cursor[e] = off;
            int tiles = (cnt + TILE_M - 1)/TILE_M;
            for (int i = 0; i < tiles; ++i){
                g_tile_expert[nt] = e;
                g_tile_row0[nt] = off + i*TILE_M;
                nt++;
            }
            off += tiles*TILE_M;
        }
        g_num_tiles = nt;
    }
    __syncthreads();
    for (int idx = threadIdx.x; idx < NTOK*(TOPK+1); idx += 1024){
        int t = idx/(TOPK+1), j = idx%(TOPK+1);
        if (j < TOPK){
            int e = g_topi[t*TOPK + j];
            float w = g_topw[t*TOPK + j];
            int r = atomicAdd(&g_cursor[e], 1);
            g_row_token[r] = t;
            g_row_weight[r] = w;
            g_tok_rows[t*(TOPK+1) + j] = r;
        } else {
            int r = g_offset[NEXP] + t;
            g_row_token[r] = t;
            g_row_weight[r] = 1.0f;
            g_tok_rows[t*(TOPK+1) + j] = r;
        }
    }
}

// ------------------- FC1: swiglu(Xg @ Wfc), fp16 m16n8k16, CTA 128x256 ----------
// R8-exact: 8 warps (2M x 4N), warp tile 64x64, KC=16, STAGES=4
__global__ void __launch_bounds__(256, 1) k_fc1(){
    int bx = blockIdx.x;
    int tile = bx / FC1_COLS, jb = (bx % FC1_COLS)*FC1_NOUT;
    if (tile >= g_num_tiles) return;
    int e = g_tile_expert[tile], row0 = g_tile_row0[tile];
    const __half* wbase = g_wfc_h + (size_t)e*CDIM*H2;

    extern __shared__ char smc[];
    uint32_t sb = smem_u32(smc);

    int tid = threadIdx.x, lane = tid & 31, w = tid >> 5;
    int wm = w & 1, wn = w >> 1;
    int m0 = wm*64, n0w = wn*8;
    int r = lane >> 2;

    int am = tid >> 1, ah = tid & 1;
    int tokA = g_row_token[row0 + am];
    const __half* asrc = g_xh + (size_t)tokA*CDIM + ah*8;
    uint32_t adst = (uint32_t)(am*32 + ((ah ^ ((am >> 2) & 1)) << 4));

    const __half* bsrc[2]; uint32_t bdst[2];
    #pragma unroll
    for (int i = 0; i < 2; i++){
        int idx = tid + i*256;
        int bk = idx >> 5, nb = idx & 31;
        int col0 = (nb & 1) ? (HDIM + jb + (nb >> 1)*8) : (jb + (nb >> 1)*8);
        bsrc[i] = wbase + (size_t)bk*H2 + col0;
        bdst[i] = (uint32_t)(A_BYTES + bk*512 + ((nb ^ (bk & 7)) << 4));
    }

    #pragma unroll
    for (int s = 0; s < STAGES-1; s++){
        uint32_t so = sb + s*STG_BYTES;
        CP16(so + adst, asrc + s*KC);
        #pragma unroll
        for (int i = 0; i < 2; i++)
            CP16(so + bdst[i], bsrc[i] + (size_t)s*KC*H2);
        CP_COMMIT();
    }

    float acc[4][8][4];
    #pragma unroll
    for (int i = 0; i < 4; i++)
        #pragma unroll
        for (int j = 0; j < 8; j++)
            #pragma unroll
            for (int q = 0; q < 4; q++) acc[i][j][q] = 0.0f;

    uint32_t aoff[4];
    {
        int li = lane & 7, msel = (lane >> 3) & 1, h = (lane >> 4) & 1;
        #pragma unroll
        for (int mi = 0; mi < 4; mi++){
            int m = m0 + mi*16 + msel*8 + li;
            aoff[mi] = (uint32_t)(m*32 + ((h ^ ((m >> 2) & 1)) << 4));
        }
    }
    uint32_t boff[8];
    {
        int kk = lane & 15;
        #pragma unroll
        for (int ni = 0; ni < 8; ni++){
            int nb = n0w + ni;
            boff[ni] = (uint32_t)(A_BYTES + kk*512 + ((nb ^ (kk & 7)) << 4));
        }
    }

    const int nK = CDIM/KC;   // 48
    for (int ks = 0; ks < nK; ks++){
        asm volatile("cp.async.wait_group %0;" :: "n"(STAGES-2) : "memory");
        __syncthreads();
        int t = ks + STAGES - 1;
        if (t < nK){
            uint32_t so = sb + (t % STAGES)*STG_BYTES;
            CP16(so + adst, asrc + t*KC);
            #pragma unroll
            for (int i = 0; i < 2; i++)
                CP16(so + bdst[i], bsrc[i] + (size_t)t*KC*H2);
        }
        CP_COMMIT();

        uint32_t st = sb + (ks % STAGES)*STG_BYTES;
        uint32_t a[4][4], b[8][2];
        #pragma unroll
        for (int mi = 0; mi < 4; mi++)
            LDSM4(a[mi][0], a[mi][1], a[mi][2], a[mi][3], st + aoff[mi]);
        #pragma unroll
        for (int ni = 0; ni < 8; ni++)
            LDSM2T(b[ni][0], b[ni][1], st + boff[ni]);
        #pragma unroll
        for (int mi = 0; mi < 4; mi++)
            #pragma unroll
            for (int ni = 0; ni < 8; ni++)
                mma_f16(acc[mi][ni], a[mi], b[ni]);
    }

    // epilogue: swiglu pairs (ni even = gate, ni+1 = val), write fp16
    int c2 = (lane & 3)*2;
    #pragma unroll
    for (int mi = 0; mi < 4; mi++){
        int ra = row0 + m0 + mi*16 + r;
        #pragma unroll
        for (int fe = 0; fe < 8; fe += 2){
            float* ag = acc[mi][fe];
            float* av = acc[mi][fe + 1];
            int ocol = jb + (4*wn + (fe >> 1))*8 + c2;
            __half2 h0 = __floats2half2_rn(silu_f(ag[0])*av[0], silu_f(ag[1])*av[1]);
            __half2 h1 = __floats2half2_rn(silu_f(ag[2])*av[2], silu_f(ag[3])*av[3]);
            *(__half2*)(g_act + (size_t)ra*HDIM + ocol) = h0;
            *(__half2*)(g_act + (size_t)(ra + 8)*HDIM + ocol) = h1;
        }
    }
}

// ------------------- FC2: act @ Wproj -> g_part, fp16 m16n8k16 -------------------
__global__ void __launch_bounds__(256, 1) k_fc2(){
    int bx = blockIdx.x;
    int tile = bx / FC2_COLS, jb = (bx % FC2_COLS)*BLK_N;
    if (tile >= g_num_tiles) return;
    int e = g_tile_expert[tile], row0 = g_tile_row0[tile];
    const __half* wbase = g_wpj_h + (size_t)e*HDIM*CDIM;

    extern __shared__ char smc[];
    uint32_t sb = smem_u32(smc);

    int tid = threadIdx.x, lane = tid & 31, w = tid >> 5;
    int wm = w & 1, wn = w >> 1;
    int m0 = wm*64, n0w = wn*8;
    int r = lane >> 2;

    int am = tid >> 1, ah = tid & 1;
    const __half* asrc = g_act + (size_t)(row0 + am)*HDIM + ah*8;
    uint32_t adst = (uint32_t)(am*32 + ((ah ^ ((am >> 2) & 1)) << 4));

    const __half* bsrc[2]; uint32_t bdst[2];
    #pragma unroll
    for (int i = 0; i < 2; i++){
        int idx = tid + i*256;
        int bk = idx >> 5, nb = idx & 31;
        bsrc[i] = wbase + (size_t)bk*CDIM + jb + nb*8;
        bdst[i] = (uint32_t)(A_BYTES + bk*512 + ((nb ^ (bk & 7)) << 4));
    }

    #pragma unroll
    for (int s = 0; s < STAGES-1; s++){
        uint32_t so = sb + s*STG_BYTES;
        CP16(so + adst, asrc + s*KC);
        #pragma unroll
        for (int i = 0; i < 2; i++)
            CP16(so + bdst[i], bsrc[i] + (size_t)s*KC*CDIM);
        CP_COMMIT();
    }

    float acc[4][8][4];
    #pragma unroll
    for (int i = 0; i < 4; i++)
        #pragma unroll
        for (int j = 0; j < 8; j++)
            #pragma unroll
            for (int q = 0; q < 4; q++) acc[i][j][q] = 0.0f;

    uint32_t aoff[4];
    {
        int li = lane & 7, msel = (lane >> 3) & 1, h = (lane >> 4) & 1;
        #pragma unroll
        for (int mi = 0; mi < 4; mi++){
            int m = m0 + mi*16 + msel*8 + li;
            aoff[mi] = (uint32_t)(m*32 + ((h ^ ((m >> 2) & 1)) << 4));
        }
    }
    uint32_t boff[8];
    {
        int kk = lane & 15;
        #pragma unroll
        for (int ni = 0; ni < 8; ni++){
            int nb = n0w + ni;
            boff[ni] = (uint32_t)(A_BYTES + kk*512 + ((nb ^ (kk & 7)) << 4));
        }
    }

    const int nK = HDIM/KC;   // 192
    for (int ks = 0; ks < nK; ks++){
        asm volatile("cp.async.wait_group %0;" :: "n"(STAGES-2) : "memory");
        __syncthreads();
        int t = ks + STAGES - 1;
        if (t < nK){
            uint32_t so = sb + (t % STAGES)*STG_BYTES;
            CP16(so + adst, asrc + t*KC);
            #pragma unroll
            for (int i = 0; i < 2; i++)
                CP16(so + bdst[i], bsrc[i] + (size_t)t*KC*CDIM);
        }
        CP_COMMIT();

        uint32_t st = sb + (ks % STAGES)*STG_BYTES;
        uint32_t a[4][4], b[8][2];
        #pragma unroll
        for (int mi = 0; mi < 4; mi++)
            LDSM4(a[mi][0], a[mi][1], a[mi][2], a[mi][3], st + aoff[mi]);
        #pragma unroll
        for (int ni = 0; ni < 8; ni++)
            LDSM2T(b[ni][0], b[ni][1], st + boff[ni]);
        #pragma unroll
        for (int mi = 0; mi < 4; mi++)
            #pragma unroll
            for (int ni = 0; ni < 8; ni++)
                mma_f16(acc[mi][ni], a[mi], b[ni]);
    }

    int c2 = (lane & 3)*2;
    #pragma unroll
    for (int mi = 0; mi < 4; mi++){
        int ra = row0 + m0 + mi*16 + r;
        #pragma unroll
        for (int ni = 0; ni < 8; ni++){
            int ocol = jb + wn*64 + ni*8 + c2;
            float2 o0, o1;
            o0.x = acc[mi][ni][0]; o0.y = acc[mi][ni][1];
            o1.x = acc[mi][ni][2]; o1.y = acc[mi][ni][3];
            *(float2*)(g_part + (size_t)ra*CDIM + ocol) = o0;
            *(float2*)(g_part + (size_t)(ra + 8)*CDIM + ocol) = o1;
        }
    }
}

// ------------------- gather: out[t] = sum_j w_j * part[r_j] -------------------
__global__ void k_gather(float* __restrict__ out){
    __shared__ int rs[TOPK+1];
    __shared__ float ws[TOPK+1];
    int t = blockIdx.x;
    if (threadIdx.x < TOPK+1){
        int r = g_tok_rows[t*(TOPK+1) + threadIdx.x];
        rs[threadIdx.x] = r;
        ws[threadIdx.x] = g_row_weight[r];
    }
    __syncthreads();
    int c = threadIdx.x*4;
    float4 acc = make_float4(0.f, 0.f, 0.f, 0.f);
    #pragma unroll
    for (int j = 0; j < TOPK+1; j++){
        const float4 p = *(const float4*)(g_part + (size_t)rs[j]*CDIM + c);
        float w = ws[j];
        acc.x += w*p.x; acc.y += w*p.y; acc.z += w*p.z; acc.w += w*p.w;
    }
    *(float4*)(out + (size_t)t*CDIM + c) = acc;
}

// ------------------- launch -------------------
extern "C" void kernel_launch(void* const* d_in, const int* in_sizes, int n_in,
                              void* d_out, int out_size){
    const float* x              = (const float*)d_in[0];
    const float* w_shared_fc    = (const float*)d_in[1];
    const float* w_shared_proj  = (const float*)d_in[2];
    const float* w_experts_fc   = (const float*)d_in[3];
    const float* w_experts_proj = (const float*)d_in[4];
    const float* w_gate         = (const float*)d_in[5];
    const float* expert_bias    = (const float*)d_in[6];
    float* out = (float*)d_out;

    cudaFuncSetAttribute(k_fc1, cudaFuncAttributeMaxDynamicSharedMemorySize, FC_SMEM);
    cudaFuncSetAttribute(k_fc2, cudaFuncAttributeMaxDynamicSharedMemorySize, FC_SMEM);

    // launch #1: vectorized conversions + init fused
    k_prep<<<2368, 256>>>(x, w_shared_fc, w_experts_fc, w_shared_proj, w_experts_proj);
    // launch #2
    k_gate<<<NTOK/8, 256>>>(x, w_gate, expert_bias);
    // launch #3
    k_scanfill<<<1, 1024>>>();
    // launch #4  <- ncu captures this one
    k_fc1<<<MAX_TILES*FC1_COLS, 256, FC_SMEM>>>();
    // launch #5
    k_fc2<<<MAX_TILES*FC2_COLS, 256, FC_SMEM>>>();
    // launch #6
    k_gather<<<NTOK, CDIM/4>>>(out);
}